// round 2
// baseline (speedup 1.0000x reference)
#include <cuda_runtime.h>
#include <math.h>

#define NN 2048
#define DD 64
#define BH 32          // B*H = 4*8
#define BM 64          // query rows per CTA
#define BN 32          // key cols per iteration
#define ATT_SCALE 0.125f   // 64^-0.5

__global__ __launch_bounds__(256, 2)
void selfatt_kernel(const float* __restrict__ Q, const float* __restrict__ K,
                    const float* __restrict__ V, const unsigned int* __restrict__ M,
                    float* __restrict__ O)
{
    // All inner-loop operands stored so reads are contiguous float4s.
    __shared__ float QsT[DD][68];   // [d][r]   (pad 68 -> 16B-aligned rows, conflict-spread)
    __shared__ float KsT[DD][36];   // [d][c]
    __shared__ float Vs [BN][DD];   // [m][d]
    __shared__ float SsT[BN][68];   // [c][r]

    const int tid = threadIdx.x;
    const int tx = tid & 15;        // 0..15
    const int ty = tid >> 4;        // 0..15
    const int r0 = ty * 4;          // 4 query rows per thread
    const int c0 = tx * 2;          // 2 key cols per thread (GEMM1)
    const int d0 = tx * 4;          // 4 head dims per thread (GEMM2)

    const int bh = blockIdx.y;
    const int q0 = blockIdx.x * BM;

    const float* qb = Q + (size_t)bh * NN * DD;
    const float* kb = K + (size_t)bh * NN * DD;
    const float* vb = V + (size_t)bh * NN * DD;
    const unsigned int* mb = M + (size_t)bh * NN * NN;

    // ---- load Q tile transposed: QsT[d][r] = q[q0+r][d] ----
    for (int i = tid; i < BM * 16; i += 256) {
        int r = i >> 4, d4 = (i & 15) << 2;
        float4 t = *(const float4*)(qb + (size_t)(q0 + r) * DD + d4);
        QsT[d4 + 0][r] = t.x; QsT[d4 + 1][r] = t.y;
        QsT[d4 + 2][r] = t.z; QsT[d4 + 3][r] = t.w;
    }

    float acc[4][4];
    #pragma unroll
    for (int i = 0; i < 4; i++)
        #pragma unroll
        for (int j = 0; j < 4; j++) acc[i][j] = 0.0f;

    for (int kt = 0; kt < NN / BN; kt++) {
        __syncthreads();   // prev GEMM2 done reading KsT/Vs/SsT (also covers Q-load on iter 0)

        // ---- load K tile transposed: KsT[d][c] = k[kt*BN+c][d] ----
        for (int i = tid; i < BN * 16; i += 256) {
            int c = i >> 4, d4 = (i & 15) << 2;
            float4 t = *(const float4*)(kb + (size_t)(kt * BN + c) * DD + d4);
            KsT[d4 + 0][c] = t.x; KsT[d4 + 1][c] = t.y;
            KsT[d4 + 2][c] = t.z; KsT[d4 + 3][c] = t.w;
        }
        // ---- load V tile straight: Vs[m][d] ----
        for (int i = tid; i < BN * 16; i += 256) {
            int m = i >> 4, d4 = (i & 15) << 2;
            *(float4*)&Vs[m][d4] = *(const float4*)(vb + (size_t)(kt * BN + m) * DD + d4);
        }
        __syncthreads();

        // ---- GEMM1: s[r][c] = sum_d QsT[d][r] * KsT[d][c]  (4x2 per thread) ----
        float s0[4], s1[4];
        #pragma unroll
        for (int i = 0; i < 4; i++) { s0[i] = 0.0f; s1[i] = 0.0f; }
        #pragma unroll 8
        for (int dd = 0; dd < DD; dd++) {
            float4 a = *(const float4*)&QsT[dd][r0];
            float b0 = KsT[dd][c0];
            float b1 = KsT[dd][c0 + 1];
            s0[0] += a.x * b0; s0[1] += a.y * b0; s0[2] += a.z * b0; s0[3] += a.w * b0;
            s1[0] += a.x * b1; s1[1] += a.y * b1; s1[2] += a.z * b1; s1[3] += a.w * b1;
        }

        // ---- tanh + mask (mask word != 0 -> drop), write SsT[c][r] ----
        // Mask stored as 4-byte elements (bool normalized to int32 or float32 by the
        // harness); nonzero bit-pattern == True for both encodings.
        float w0[4], w1[4];
        #pragma unroll
        for (int i = 0; i < 4; i++) {
            const unsigned int* mp = mb + (size_t)(q0 + r0 + i) * NN + kt * BN + c0;
            unsigned int m0 = mp[0], m1 = mp[1];
            w0[i] = m0 ? 0.0f : tanhf(s0[i] * ATT_SCALE);
            w1[i] = m1 ? 0.0f : tanhf(s1[i] * ATT_SCALE);
        }
        *(float4*)&SsT[c0    ][r0] = make_float4(w0[0], w0[1], w0[2], w0[3]);
        *(float4*)&SsT[c0 + 1][r0] = make_float4(w1[0], w1[1], w1[2], w1[3]);
        __syncthreads();

        // ---- GEMM2: acc[r][d] += sum_m SsT[m][r] * Vs[m][d]  (4x4 per thread) ----
        #pragma unroll 8
        for (int m = 0; m < BN; m++) {
            float4 a = *(const float4*)&SsT[m][r0];
            float4 b = *(const float4*)&Vs[m][d0];
            acc[0][0] += a.x * b.x; acc[0][1] += a.x * b.y; acc[0][2] += a.x * b.z; acc[0][3] += a.x * b.w;
            acc[1][0] += a.y * b.x; acc[1][1] += a.y * b.y; acc[1][2] += a.y * b.z; acc[1][3] += a.y * b.w;
            acc[2][0] += a.z * b.x; acc[2][1] += a.z * b.y; acc[2][2] += a.z * b.z; acc[2][3] += a.z * b.w;
            acc[3][0] += a.w * b.x; acc[3][1] += a.w * b.y; acc[3][2] += a.w * b.z; acc[3][3] += a.w * b.w;
        }
    }

    // ---- write output: O[bh][q0+r][d] ----
    #pragma unroll
    for (int i = 0; i < 4; i++) {
        float4 o = make_float4(acc[i][0], acc[i][1], acc[i][2], acc[i][3]);
        *(float4*)(O + ((size_t)bh * NN + q0 + r0 + i) * DD + d0) = o;
    }
}

extern "C" void kernel_launch(void* const* d_in, const int* in_sizes, int n_in,
                              void* d_out, int out_size)
{
    const float* q = (const float*)d_in[0];
    const float* k = (const float*)d_in[1];
    const float* v = (const float*)d_in[2];
    const unsigned int* m = (const unsigned int*)d_in[3];
    float* o = (float*)d_out;

    dim3 grid(NN / BM, BH);   // 32 x 32 = 1024 CTAs
    selfatt_kernel<<<grid, 256>>>(q, k, v, m, o);
}

// round 3
// speedup vs baseline: 1.3930x; 1.3930x over previous
#include <cuda_runtime.h>
#include <math.h>

#define NN 2048
#define DD 64
#define BH 32          // B*H
#define BM 64          // query rows per CTA
#define BN 32          // key cols per k-iteration
#define NKT (NN / BN)  // 64 k-iterations
#define ATT_SCALE 0.125f

// Strides chosen for conflict-free fragment LDS:
//  A-side arrays (rows indexed by lane>>2, cols by lane&3): stride % 32 == 4
//  B-side arrays (rows indexed by lane&3, cols by lane>>2): stride % 32 == 8
#define QS_STR 68
#define KS_STR 40
#define VS_STR 72
#define SS_STR 36

__device__ __forceinline__ float f2tf32(float x) {
    unsigned y;
    asm("cvt.rna.tf32.f32 %0, %1;" : "=r"(y) : "f"(x));
    return __uint_as_float(y);
}

__device__ __forceinline__ void mma8(float c[4], const float a[4], const float b[2]) {
    asm volatile(
        "mma.sync.aligned.m16n8k8.row.col.f32.tf32.tf32.f32 "
        "{%0,%1,%2,%3}, {%4,%5,%6,%7}, {%8,%9}, {%0,%1,%2,%3};"
        : "+f"(c[0]), "+f"(c[1]), "+f"(c[2]), "+f"(c[3])
        : "r"(__float_as_uint(a[0])), "r"(__float_as_uint(a[1])),
          "r"(__float_as_uint(a[2])), "r"(__float_as_uint(a[3])),
          "r"(__float_as_uint(b[0])), "r"(__float_as_uint(b[1])));
}

__global__ __launch_bounds__(128)
void selfatt_mma_kernel(const float* __restrict__ Q, const float* __restrict__ K,
                        const float* __restrict__ V, const unsigned int* __restrict__ M,
                        float* __restrict__ O)
{
    __shared__ float Qs [DD][QS_STR];   // [r][d]  tf32, A operand GEMM1 (only BM=64 rows used)
    __shared__ float KsT[DD][KS_STR];   // [d][key] tf32, B operand GEMM1
    __shared__ float Vs [BN][VS_STR];   // [m][d]  tf32, B operand GEMM2
    __shared__ float Ss [BM][SS_STR];   // mask bits (phase 1) then S tf32 (phase 2), A operand GEMM2

    const int tid  = threadIdx.x;
    const int lane = tid & 31;
    const int warp = tid >> 5;          // 0..3
    const int wm   = warp >> 1;         // 0..1  (m half: 32 rows)
    const int wn   = warp & 1;          // 0..1  (n half)
    const int lg   = lane >> 2;         // group id 0..7
    const int lt   = lane & 3;          // thread-in-group 0..3

    const int bh = blockIdx.y;
    const int q0 = blockIdx.x * BM;

    const float* qb = Q + (size_t)bh * NN * DD;
    const float* kb = K + (size_t)bh * NN * DD;
    const float* vb = V + (size_t)bh * NN * DD;
    const unsigned int* mb = M + (size_t)bh * NN * NN;

    // ---- load Q tile once (tf32-converted): Qs[r][d] ----
    for (int i = tid; i < BM * (DD / 4); i += 128) {
        int r = i >> 4, d4 = (i & 15) << 2;
        float4 t = *(const float4*)(qb + (size_t)(q0 + r) * DD + d4);
        t.x = f2tf32(t.x); t.y = f2tf32(t.y); t.z = f2tf32(t.z); t.w = f2tf32(t.w);
        *(float4*)&Qs[r][d4] = t;
    }

    // O accumulators: warp tile 32(m) x 32(n) -> 2 mt x 4 nt x 4 regs
    float oacc[2][4][4];
    #pragma unroll
    for (int i = 0; i < 2; i++)
        #pragma unroll
        for (int j = 0; j < 4; j++)
            #pragma unroll
            for (int l = 0; l < 4; l++) oacc[i][j][l] = 0.0f;

    for (int kt = 0; kt < NKT; kt++) {
        const int keyb = kt * BN;
        __syncthreads();   // previous iter's GEMM2 / loads done

        // ---- K tile transposed: KsT[d][key] (tf32) ----
        for (int i = tid; i < BN * (DD / 4); i += 128) {
            int key = i >> 4, d4 = (i & 15) << 2;
            float4 t = *(const float4*)(kb + (size_t)(keyb + key) * DD + d4);
            KsT[d4 + 0][key] = f2tf32(t.x); KsT[d4 + 1][key] = f2tf32(t.y);
            KsT[d4 + 2][key] = f2tf32(t.z); KsT[d4 + 3][key] = f2tf32(t.w);
        }
        // ---- V tile straight: Vs[m][d] (tf32) ----
        for (int i = tid; i < BN * (DD / 4); i += 128) {
            int m = i >> 4, d4 = (i & 15) << 2;
            float4 t = *(const float4*)(vb + (size_t)(keyb + m) * DD + d4);
            t.x = f2tf32(t.x); t.y = f2tf32(t.y); t.z = f2tf32(t.z); t.w = f2tf32(t.w);
            *(float4*)&Vs[m][d4] = t;
        }
        // ---- mask tile (raw uint bits) staged into Ss ----
        for (int i = tid; i < BM * (BN / 4); i += 128) {
            int r = i >> 3, c4 = (i & 7) << 2;
            uint4 t = *(const uint4*)(mb + (size_t)(q0 + r) * NN + keyb + c4);
            *(uint4*)&Ss[r][c4] = t;
        }
        __syncthreads();

        // ---- GEMM1: S[64x32] = Q . K^T  (warp tile 32x16) ----
        float sc[2][2][4];
        #pragma unroll
        for (int i = 0; i < 2; i++)
            #pragma unroll
            for (int j = 0; j < 2; j++)
                #pragma unroll
                for (int l = 0; l < 4; l++) sc[i][j][l] = 0.0f;

        #pragma unroll
        for (int k8 = 0; k8 < DD / 8; k8++) {
            const int kc = k8 * 8 + lt;
            float a[2][4];
            #pragma unroll
            for (int mt = 0; mt < 2; mt++) {
                const int ar = wm * 32 + mt * 16 + lg;
                a[mt][0] = Qs[ar][kc];     a[mt][1] = Qs[ar + 8][kc];
                a[mt][2] = Qs[ar][kc + 4]; a[mt][3] = Qs[ar + 8][kc + 4];
            }
            float b[2][2];
            #pragma unroll
            for (int nt = 0; nt < 2; nt++) {
                const int bc = wn * 16 + nt * 8 + lg;
                b[nt][0] = KsT[k8 * 8 + lt][bc];
                b[nt][1] = KsT[k8 * 8 + 4 + lt][bc];
            }
            #pragma unroll
            for (int mt = 0; mt < 2; mt++)
                #pragma unroll
                for (int nt = 0; nt < 2; nt++)
                    mma8(sc[mt][nt], a[mt], b[nt]);
        }

        // ---- mask (from Ss bits) + tanh ----
        float w[2][2][4];
        #pragma unroll
        for (int mt = 0; mt < 2; mt++) {
            const int r = wm * 32 + mt * 16 + lg;
            #pragma unroll
            for (int nt = 0; nt < 2; nt++) {
                const int c = wn * 16 + nt * 8 + 2 * lt;
                unsigned m0 = __float_as_uint(Ss[r][c]);
                unsigned m1 = __float_as_uint(Ss[r][c + 1]);
                unsigned m2 = __float_as_uint(Ss[r + 8][c]);
                unsigned m3 = __float_as_uint(Ss[r + 8][c + 1]);
                w[mt][nt][0] = m0 ? 0.0f : f2tf32(tanhf(sc[mt][nt][0] * ATT_SCALE));
                w[mt][nt][1] = m1 ? 0.0f : f2tf32(tanhf(sc[mt][nt][1] * ATT_SCALE));
                w[mt][nt][2] = m2 ? 0.0f : f2tf32(tanhf(sc[mt][nt][2] * ATT_SCALE));
                w[mt][nt][3] = m3 ? 0.0f : f2tf32(tanhf(sc[mt][nt][3] * ATT_SCALE));
            }
        }
        __syncthreads();   // all mask reads done before overwriting Ss

        // ---- write S (tf32) to Ss ----
        #pragma unroll
        for (int mt = 0; mt < 2; mt++) {
            const int r = wm * 32 + mt * 16 + lg;
            #pragma unroll
            for (int nt = 0; nt < 2; nt++) {
                const int c = wn * 16 + nt * 8 + 2 * lt;
                *(float2*)&Ss[r][c]     = make_float2(w[mt][nt][0], w[mt][nt][1]);
                *(float2*)&Ss[r + 8][c] = make_float2(w[mt][nt][2], w[mt][nt][3]);
            }
        }
        __syncthreads();

        // ---- GEMM2: O[64x64] += S . V  (warp tile 32x32, k = BN = 32) ----
        #pragma unroll
        for (int k8 = 0; k8 < BN / 8; k8++) {
            const int kc = k8 * 8 + lt;
            float a[2][4];
            #pragma unroll
            for (int mt = 0; mt < 2; mt++) {
                const int ar = wm * 32 + mt * 16 + lg;
                a[mt][0] = Ss[ar][kc];     a[mt][1] = Ss[ar + 8][kc];
                a[mt][2] = Ss[ar][kc + 4]; a[mt][3] = Ss[ar + 8][kc + 4];
            }
            #pragma unroll
            for (int nt = 0; nt < 4; nt++) {
                float b[2];
                const int bc = wn * 32 + nt * 8 + lg;
                b[0] = Vs[k8 * 8 + lt][bc];
                b[1] = Vs[k8 * 8 + 4 + lt][bc];
                #pragma unroll
                for (int mt = 0; mt < 2; mt++)
                    mma8(oacc[mt][nt], a[mt], b);
            }
        }
    }

    // ---- epilogue: write O ----
    #pragma unroll
    for (int mt = 0; mt < 2; mt++) {
        const int r = wm * 32 + mt * 16 + lg;
        #pragma unroll
        for (int nt = 0; nt < 4; nt++) {
            const int c = wn * 32 + nt * 8 + 2 * lt;
            float* op0 = O + ((size_t)bh * NN + q0 + r) * DD + c;
            float* op8 = O + ((size_t)bh * NN + q0 + r + 8) * DD + c;
            *(float2*)op0 = make_float2(oacc[mt][nt][0], oacc[mt][nt][1]);
            *(float2*)op8 = make_float2(oacc[mt][nt][2], oacc[mt][nt][3]);
        }
    }
}

extern "C" void kernel_launch(void* const* d_in, const int* in_sizes, int n_in,
                              void* d_out, int out_size)
{
    const float* q = (const float*)d_in[0];
    const float* k = (const float*)d_in[1];
    const float* v = (const float*)d_in[2];
    const unsigned int* m = (const unsigned int*)d_in[3];
    float* o = (float*)d_out;

    dim3 grid(NN / BM, BH);   // 32 x 32
    selfatt_mma_kernel<<<grid, 128>>>(q, k, v, m, o);
}

// round 4
// speedup vs baseline: 3.5250x; 2.5305x over previous
#include <cuda_runtime.h>

#define NN 2048
#define DD 64
#define BM 128
#define BN 32
#define NKT (NN / BN)
#define ATT_SCALE 0.125f

#define KSTR 40            // ( % 32 == 8 ) conflict-free B-frag reads
#define VSTR 72            // ( % 32 == 8 )
#define QSTR 68            // ( % 32 == 4 ) conflict-free A-frag reads
#define KBUF (DD * KSTR)   // 2560 floats per buffer
#define VBUF (BN * VSTR)   // 2304 floats per buffer
#define SMEM_FLOATS (2 * KBUF + 2 * VBUF)   // 9728 floats = 38.9 KB (Q stages here too)

__device__ __forceinline__ float f2tf32(float x) {
    unsigned y; asm("cvt.rna.tf32.f32 %0, %1;" : "=r"(y) : "f"(x));
    return __uint_as_float(y);
}
__device__ __forceinline__ float tanh_fast(float x) {
    float y; asm("tanh.approx.f32 %0, %1;" : "=f"(y) : "f"(x));
    return y;
}
__device__ __forceinline__ void mma8(float c[4], const float a[4], float b0, float b1) {
    asm volatile(
        "mma.sync.aligned.m16n8k8.row.col.f32.tf32.tf32.f32 "
        "{%0,%1,%2,%3}, {%4,%5,%6,%7}, {%8,%9}, {%0,%1,%2,%3};"
        : "+f"(c[0]), "+f"(c[1]), "+f"(c[2]), "+f"(c[3])
        : "r"(__float_as_uint(a[0])), "r"(__float_as_uint(a[1])),
          "r"(__float_as_uint(a[2])), "r"(__float_as_uint(a[3])),
          "r"(__float_as_uint(b0)),   "r"(__float_as_uint(b1)));
}

__global__ __launch_bounds__(256, 2)
void selfatt_mma2_kernel(const float* __restrict__ Q, const float* __restrict__ K,
                         const float* __restrict__ V, const unsigned int* __restrict__ M,
                         float* __restrict__ O)
{
    __shared__ __align__(16) float smem[SMEM_FLOATS];

    const int tid  = threadIdx.x;
    const int lane = tid & 31;
    const int w    = tid >> 5;          // 0..7
    const int lg   = lane >> 2;         // 0..7
    const int lt   = lane & 3;          // 0..3
    const int r0   = w * 16;            // this warp's 16 S-rows

    const int bh = blockIdx.y;
    const int q0 = blockIdx.x * BM;

    const float* qb = Q + (size_t)bh * NN * DD;
    const float* kb = K + (size_t)bh * NN * DD;
    const float* vb = V + (size_t)bh * NN * DD;
    const unsigned int* mb = M + (size_t)bh * NN * NN;

    // per-thread load mappings for K/V tiles
    const int k_key = tid & 31;                 // K row within tile
    const int k_d0  = (tid >> 5) * 4;           // K col base (j adds +32)
    const int v_m0  = tid >> 4;                 // V row (j adds +16)
    const int v_d   = (tid & 15) * 4;           // V col base

    // ---- stage Q (tf32) into smem, grab A-fragments into registers, then free it ----
    for (int i = tid; i < BM * (DD / 4); i += 256) {
        int r = i >> 4, d4 = (i & 15) << 2;
        float4 t = *(const float4*)(qb + (size_t)(q0 + r) * DD + d4);
        float* dst = smem + r * QSTR + d4;
        dst[0] = f2tf32(t.x); dst[1] = f2tf32(t.y);
        dst[2] = f2tf32(t.z); dst[3] = f2tf32(t.w);
    }
    __syncthreads();

    float qa[8][4];
    #pragma unroll
    for (int k8 = 0; k8 < 8; k8++) {
        const float* p0 = smem + (r0 + lg) * QSTR + k8 * 8;
        const float* p8 = smem + (r0 + 8 + lg) * QSTR + k8 * 8;
        qa[k8][0] = p0[lt];     qa[k8][1] = p8[lt];
        qa[k8][2] = p0[lt + 4]; qa[k8][3] = p8[lt + 4];
    }
    __syncthreads();   // Q staging dead; smem becomes K/V double buffers

    // ---- load tile 0 into buffer 0 ----
    {
        float* ks = smem;              // Kbuf[0]
        #pragma unroll
        for (int j = 0; j < 2; j++) {
            int d0 = k_d0 + j * 32;
            float4 t = *(const float4*)(kb + (size_t)k_key * DD + d0);
            ks[(d0 + 0) * KSTR + k_key] = f2tf32(t.x);
            ks[(d0 + 1) * KSTR + k_key] = f2tf32(t.y);
            ks[(d0 + 2) * KSTR + k_key] = f2tf32(t.z);
            ks[(d0 + 3) * KSTR + k_key] = f2tf32(t.w);
        }
        float* vs = smem + 2 * KBUF;   // Vbuf[0]
        #pragma unroll
        for (int j = 0; j < 2; j++) {
            int m = v_m0 + j * 16;
            float4 t = *(const float4*)(vb + (size_t)m * DD + v_d);
            float* d = vs + m * VSTR + v_d;
            d[0] = f2tf32(t.x); d[1] = f2tf32(t.y);
            d[2] = f2tf32(t.z); d[3] = f2tf32(t.w);
        }
    }
    __syncthreads();

    float oacc[8][4];
    #pragma unroll
    for (int nt = 0; nt < 8; nt++)
        #pragma unroll
        for (int i = 0; i < 4; i++) oacc[nt][i] = 0.0f;

    const unsigned int* mrow0 = mb + (size_t)(q0 + r0 + lg) * NN + 2 * lt;
    const unsigned int* mrow8 = mrow0 + 8 * (size_t)NN;

    int p = 0;
    for (int kt = 0; kt < NKT; kt++) {
        const int keyb = kt * BN;
        const bool pf = (kt + 1 < NKT);

        // prefetch next K/V tile into registers (consumed at iter bottom)
        float4 kf0, kf1, vf0, vf1;
        if (pf) {
            const int nb = keyb + BN;
            kf0 = *(const float4*)(kb + (size_t)(nb + k_key) * DD + k_d0);
            kf1 = *(const float4*)(kb + (size_t)(nb + k_key) * DD + k_d0 + 32);
            vf0 = *(const float4*)(vb + (size_t)(nb + v_m0) * DD + v_d);
            vf1 = *(const float4*)(vb + (size_t)(nb + v_m0 + 16) * DD + v_d);
        }
        // prefetch mask for this tile (used after GEMM1)
        uint2 mk0[4], mk8[4];
        #pragma unroll
        for (int nt = 0; nt < 4; nt++) {
            mk0[nt] = *(const uint2*)(mrow0 + keyb + nt * 8);
            mk8[nt] = *(const uint2*)(mrow8 + keyb + nt * 8);
        }

        // ---- GEMM1: S[16x32] = Q16x64 . K^T ----
        const float* Kp = smem + p * KBUF;
        float sc[4][4];
        #pragma unroll
        for (int nt = 0; nt < 4; nt++)
            #pragma unroll
            for (int i = 0; i < 4; i++) sc[nt][i] = 0.0f;

        #pragma unroll
        for (int k8 = 0; k8 < 8; k8++) {
            const float* kc0 = Kp + (k8 * 8 + lt) * KSTR + lg;
            const float* kc1 = Kp + (k8 * 8 + 4 + lt) * KSTR + lg;
            #pragma unroll
            for (int nt = 0; nt < 4; nt++)
                mma8(sc[nt], qa[k8], kc0[nt * 8], kc1[nt * 8]);
        }

        // ---- mask + tanh + C->A shuffle + GEMM2 per 8-wide k-block ----
        const float* Vp = smem + 2 * KBUF + p * VBUF;
        #pragma unroll
        for (int kb8 = 0; kb8 < 4; kb8++) {
            float w0 = mk0[kb8].x ? 0.0f : tanh_fast(sc[kb8][0] * ATT_SCALE);
            float w1 = mk0[kb8].y ? 0.0f : tanh_fast(sc[kb8][1] * ATT_SCALE);
            float w2 = mk8[kb8].x ? 0.0f : tanh_fast(sc[kb8][2] * ATT_SCALE);
            float w3 = mk8[kb8].y ? 0.0f : tanh_fast(sc[kb8][3] * ATT_SCALE);

            // transpose C-frag (cols {2lt,2lt+1}) -> A-frag (cols {lt,lt+4})
            const int s0 = (lane & 28) | (lt >> 1);
            const int s1 = s0 + 2;
            float t0, t1, aS[4];
            t0 = __shfl_sync(0xffffffffu, w0, s0);
            t1 = __shfl_sync(0xffffffffu, w1, s0);
            aS[0] = (lt & 1) ? t1 : t0;
            t0 = __shfl_sync(0xffffffffu, w0, s1);
            t1 = __shfl_sync(0xffffffffu, w1, s1);
            aS[2] = (lt & 1) ? t1 : t0;
            t0 = __shfl_sync(0xffffffffu, w2, s0);
            t1 = __shfl_sync(0xffffffffu, w3, s0);
            aS[1] = (lt & 1) ? t1 : t0;
            t0 = __shfl_sync(0xffffffffu, w2, s1);
            t1 = __shfl_sync(0xffffffffu, w3, s1);
            aS[3] = (lt & 1) ? t1 : t0;
            aS[0] = f2tf32(aS[0]); aS[1] = f2tf32(aS[1]);
            aS[2] = f2tf32(aS[2]); aS[3] = f2tf32(aS[3]);

            const float* vc0 = Vp + (kb8 * 8 + lt) * VSTR + lg;
            const float* vc1 = Vp + (kb8 * 8 + 4 + lt) * VSTR + lg;
            #pragma unroll
            for (int nt = 0; nt < 8; nt++)
                mma8(oacc[nt], aS, vc0[nt * 8], vc1[nt * 8]);
        }

        // ---- commit prefetched tile into the other buffer ----
        if (pf) {
            float* kn = smem + (p ^ 1) * KBUF;
            kn[(k_d0 + 0) * KSTR + k_key] = f2tf32(kf0.x);
            kn[(k_d0 + 1) * KSTR + k_key] = f2tf32(kf0.y);
            kn[(k_d0 + 2) * KSTR + k_key] = f2tf32(kf0.z);
            kn[(k_d0 + 3) * KSTR + k_key] = f2tf32(kf0.w);
            kn[(k_d0 + 32) * KSTR + k_key] = f2tf32(kf1.x);
            kn[(k_d0 + 33) * KSTR + k_key] = f2tf32(kf1.y);
            kn[(k_d0 + 34) * KSTR + k_key] = f2tf32(kf1.z);
            kn[(k_d0 + 35) * KSTR + k_key] = f2tf32(kf1.w);
            float* vn = smem + 2 * KBUF + (p ^ 1) * VBUF;
            float* d0p = vn + v_m0 * VSTR + v_d;
            d0p[0] = f2tf32(vf0.x); d0p[1] = f2tf32(vf0.y);
            d0p[2] = f2tf32(vf0.z); d0p[3] = f2tf32(vf0.w);
            float* d1p = vn + (v_m0 + 16) * VSTR + v_d;
            d1p[0] = f2tf32(vf1.x); d1p[1] = f2tf32(vf1.y);
            d1p[2] = f2tf32(vf1.z); d1p[3] = f2tf32(vf1.w);
        }
        __syncthreads();
        p ^= 1;
    }

    // ---- epilogue ----
    #pragma unroll
    for (int nt = 0; nt < 8; nt++) {
        float* o0 = O + ((size_t)bh * NN + q0 + r0 + lg) * DD + nt * 8 + 2 * lt;
        *(float2*)o0            = make_float2(oacc[nt][0], oacc[nt][1]);
        *(float2*)(o0 + 8 * DD) = make_float2(oacc[nt][2], oacc[nt][3]);
    }
}

extern "C" void kernel_launch(void* const* d_in, const int* in_sizes, int n_in,
                              void* d_out, int out_size)
{
    const float* q = (const float*)d_in[0];
    const float* k = (const float*)d_in[1];
    const float* v = (const float*)d_in[2];
    const unsigned int* m = (const unsigned int*)d_in[3];
    float* o = (float*)d_out;

    dim3 grid(NN / BM, 32);   // 16 x 32 = 512 CTAs
    selfatt_mma2_kernel<<<grid, 256>>>(q, k, v, m, o);
}